// round 12
// baseline (speedup 1.0000x reference)
#include <cuda_runtime.h>
#include <stdint.h>

#define BDIM    256                  // batch rows
#define SDIM    2048                 // sequence positions
#define VDIM    128000               // vocab
#define THREADS 512                  // scatter kernel block
#define PER     (SDIM / THREADS)     // 4
#define HSIZE   4096
#define NWARPS  (THREADS / 32)       // 16

#define WPR         (VDIM / 32)      // bitmap words per row = 4000
#define CHUNK       128              // floats per warp-chunk
#define CPR         (VDIM / CHUNK)   // chunks per row = 1000
#define FILL_THR    256
#define FILL_WARPS  (FILL_THR / 32)  // 8
#define CHUNKS_PER_WARP 5
#define FILL_CTAS_X (CPR / (FILL_WARPS * CHUNKS_PER_WARP))  // 25

__device__ unsigned g_bitmap[BDIM * WPR];   // 4 MB; zero at load, restored by fill

__device__ __forceinline__ float block_reduce_max(float v, float* red) {
    __syncthreads();
    #pragma unroll
    for (int o = 16; o; o >>= 1)
        v = fmaxf(v, __shfl_xor_sync(0xffffffffu, v, o));
    int w = threadIdx.x >> 5, l = threadIdx.x & 31;
    if (l == 0) red[w] = v;
    __syncthreads();
    if (w == 0) {
        v = (l < NWARPS) ? red[l] : -1e30f;
        #pragma unroll
        for (int o = 8; o; o >>= 1)
            v = fmaxf(v, __shfl_xor_sync(0xffffffffu, v, o));
        if (l == 0) red[0] = v;
    }
    __syncthreads();
    return red[0];
}

__device__ __forceinline__ float block_reduce_sum(float v, float* red) {
    __syncthreads();
    #pragma unroll
    for (int o = 16; o; o >>= 1)
        v += __shfl_xor_sync(0xffffffffu, v, o);
    int w = threadIdx.x >> 5, l = threadIdx.x & 31;
    if (l == 0) red[w] = v;
    __syncthreads();
    if (w == 0) {
        v = (l < NWARPS) ? red[l] : 0.0f;
        #pragma unroll
        for (int o = 8; o; o >>= 1)
            v += __shfl_xor_sync(0xffffffffu, v, o);
        if (l == 0) red[0] = v;
    }
    __syncthreads();
    return red[0];
}

// Kernel 1: softmax + dedup; winners write weight directly + set bitmap bit.
__global__ __launch_bounds__(THREADS)
void ohwa_scatter(const float* __restrict__ w_es,
                  const int* __restrict__ x32,
                  float* __restrict__ out,
                  long long out_elems) {
    const int b = blockIdx.x;
    const int t = threadIdx.x;

    const bool is64 = (x32[1] | x32[3] | x32[5] | x32[7]) == 0;
    const int stride = is64 ? 2 : 1;
    const int* __restrict__ xrow = x32 + (size_t)b * SDIM * stride;
    const float* __restrict__ wrow = w_es + (size_t)b * SDIM;

    __shared__ int   h_key[HSIZE];
    __shared__ int   h_pos[HSIZE];
    __shared__ float red[NWARPS];

    #pragma unroll
    for (int i = t; i < HSIZE; i += THREADS) {
        h_key[i] = -1;
        h_pos[i] = -1;
    }

    float e[PER];
    float m = -1e30f;
    #pragma unroll
    for (int j = 0; j < PER; j++) {
        e[j] = wrow[t + j * THREADS];
        m = fmaxf(m, e[j]);
    }
    m = block_reduce_max(m, red);          // leading sync covers hash init
    float sum = 0.0f;
    #pragma unroll
    for (int j = 0; j < PER; j++) {
        e[j] = __expf(e[j] - m);
        sum += e[j];
    }
    sum = block_reduce_sum(sum, red);
    const float inv = __frcp_rn(sum);

    long long wbase = (long long)BDIM * VDIM + (long long)b * SDIM;
    #pragma unroll
    for (int j = 0; j < PER; j++) {
        e[j] *= inv;
        long long o = wbase + t + j * THREADS;
        if (o < out_elems) out[o] = e[j];
    }

    // dedup: last position wins
    int vv[PER], slot[PER];
    #pragma unroll
    for (int j = 0; j < PER; j++) {
        int i = t + j * THREADS;
        int v = xrow[i * stride];
        vv[j] = v;
        if ((unsigned)v >= VDIM) { slot[j] = -1; continue; }
        unsigned sl = ((unsigned)v * 2654435761u) & (HSIZE - 1);
        while (true) {
            int k = h_key[sl];
            if (k == v) break;
            if (k == -1) {
                int old = atomicCAS(&h_key[sl], -1, v);
                if (old == -1 || old == v) break;
            }
            sl = (sl + 1) & (HSIZE - 1);
        }
        slot[j] = (int)sl;
        atomicMax(&h_pos[sl], i);
    }
    __syncthreads();

    // winners: write value + mark bit (fill kernel will skip these elements)
    #pragma unroll
    for (int j = 0; j < PER; j++) {
        int i = t + j * THREADS;
        if (slot[j] >= 0 && h_pos[slot[j]] == i) {
            int v = vv[j];
            out[(size_t)b * VDIM + v] = e[j];
            atomicOr(&g_bitmap[b * WPR + (v >> 5)], 1u << (v & 31));
        }
    }
}

// Kernel 2: memset-mimic masked zero fill. Warp owns 128-float chunks;
// nibble==0 lanes emit pure STG.128. Clears its bitmap words for next call.
__global__ __launch_bounds__(FILL_THR)
void ohwa_fill(float* __restrict__ out) {
    const int row  = blockIdx.y;
    const int warp = (blockIdx.x * FILL_WARPS) + (threadIdx.x >> 5);  // 0..199
    const int lane = threadIdx.x & 31;

    const float4 z4 = make_float4(0.f, 0.f, 0.f, 0.f);
    float* __restrict__ rbase = out + (size_t)row * VDIM;
    unsigned* __restrict__ bm = g_bitmap + row * WPR;

    #pragma unroll
    for (int k = 0; k < CHUNKS_PER_WARP; k++) {
        const int c = warp + k * (FILL_WARPS * FILL_CTAS_X);  // stride 200
        const int wb = c * 4;
        // all lanes load before any lane clears (single LDG precedes STG)
        unsigned word = bm[wb + (lane >> 3)];
        if (lane < 4) bm[wb + lane] = 0;
        unsigned nib = (word >> ((lane & 7) * 4)) & 0xFu;
        float* d = rbase + c * CHUNK + lane * 4;
        if (nib == 0) {
            *reinterpret_cast<float4*>(d) = z4;
        } else {
            if (!(nib & 1u)) d[0] = 0.0f;
            if (!(nib & 2u)) d[1] = 0.0f;
            if (!(nib & 4u)) d[2] = 0.0f;
            if (!(nib & 8u)) d[3] = 0.0f;
        }
    }
}

extern "C" void kernel_launch(void* const* d_in, const int* in_sizes, int n_in,
                              void* d_out, int out_size) {
    const float* w_es = (const float*)d_in[0];
    const int*   x32  = (const int*)d_in[1];
    float*       out  = (float*)d_out;
    (void)in_sizes; (void)n_in;

    ohwa_scatter<<<BDIM, THREADS>>>(w_es, x32, out, (long long)out_size);
    dim3 fgrid(FILL_CTAS_X, BDIM);
    ohwa_fill<<<fgrid, FILL_THR>>>(out);
}

// round 15
// speedup vs baseline: 3.6556x; 3.6556x over previous
#include <cuda_runtime.h>
#include <stdint.h>

#define BDIM    256                 // batch rows
#define SDIM    2048                // sequence positions
#define VDIM    128000              // vocab
#define SEGS    25                  // segments per row
#define SEGF    (VDIM / SEGS)       // 5120 floats per segment
#define CHUNKF  128                 // floats per warp-chunk (one STG.128/lane)
#define NCHUNK  (SEGF / CHUNKF)     // 40 chunks per segment
#define THREADS 256
#define PER     (SDIM / THREADS)    // 8 positions per thread
#define NWARPS  (THREADS / 32)      // 8
#define CPW     (NCHUNK / NWARPS)   // 5 chunks per warp

__device__ __forceinline__ float block_reduce_max(float v, float* red) {
    __syncthreads();
    #pragma unroll
    for (int o = 16; o; o >>= 1)
        v = fmaxf(v, __shfl_xor_sync(0xffffffffu, v, o));
    int w = threadIdx.x >> 5, l = threadIdx.x & 31;
    if (l == 0) red[w] = v;
    __syncthreads();
    if (w == 0) {
        v = (l < NWARPS) ? red[l] : -1e30f;
        #pragma unroll
        for (int o = 4; o; o >>= 1)
            v = fmaxf(v, __shfl_xor_sync(0xffffffffu, v, o));
        if (l == 0) red[0] = v;
    }
    __syncthreads();
    return red[0];
}

__device__ __forceinline__ float block_reduce_sum(float v, float* red) {
    __syncthreads();
    #pragma unroll
    for (int o = 16; o; o >>= 1)
        v += __shfl_xor_sync(0xffffffffu, v, o);
    int w = threadIdx.x >> 5, l = threadIdx.x & 31;
    if (l == 0) red[w] = v;
    __syncthreads();
    if (w == 0) {
        v = (l < NWARPS) ? red[l] : 0.0f;
        #pragma unroll
        for (int o = 4; o; o >>= 1)
            v += __shfl_xor_sync(0xffffffffu, v, o);
        if (l == 0) red[0] = v;
    }
    __syncthreads();
    return red[0];
}

// One CTA = one 5120-float segment of one row. Dedup into value-direct smem
// seg[] + per-128-float chunk flags; fill loop is 1 broadcast LDS + 1 STG.128
// per lane for unflagged chunks (99%+). Single touch per output byte.
__global__ __launch_bounds__(THREADS)
void ohwa_cf_kernel(const float* __restrict__ w_es,
                    const int* __restrict__ x32,   // raw int32 view of x
                    float* __restrict__ out,
                    long long out_elems) {
    const int s = blockIdx.x;          // segment
    const int b = blockIdx.y;          // row
    const int t = threadIdx.x;

    // dtype sniff: int64 little-endian high words are 0 for v < 2^31
    const bool is64 = (x32[1] | x32[3] | x32[5] | x32[7]) == 0;
    const int stride = is64 ? 2 : 1;
    const int* __restrict__ xrow = x32 + (size_t)b * SDIM * stride;
    const float* __restrict__ wrow = w_es + (size_t)b * SDIM;

    __shared__ int   seg[SEGF];        // -1 | position | float bits
    __shared__ int   cflag[NCHUNK];    // chunk has >=1 winner
    __shared__ float red[NWARPS];

    // --- init ---
    int4* seg4 = reinterpret_cast<int4*>(seg);
    #pragma unroll
    for (int i = t; i < SEGF / 4; i += THREADS)
        seg4[i] = make_int4(-1, -1, -1, -1);
    if (t < NCHUNK) cflag[t] = 0;

    // --- softmax over the row (redundant per segment; row is L2-hot) ---
    float e[PER];
    float m = -1e30f;
    #pragma unroll
    for (int j = 0; j < PER; j++) {
        e[j] = wrow[t + j * THREADS];
        m = fmaxf(m, e[j]);
    }
    m = block_reduce_max(m, red);      // leading sync covers smem init
    float sum = 0.0f;
    #pragma unroll
    for (int j = 0; j < PER; j++) {
        e[j] = __expf(e[j] - m);
        sum += e[j];
    }
    sum = block_reduce_sum(sum, red);
    const float inv = __frcp_rn(sum);
    #pragma unroll
    for (int j = 0; j < PER; j++)
        e[j] *= inv;                   // weight of position t + j*THREADS

    // --- Phase A: last-position-wins dedup (direct-mapped, atomicMax) ---
    const int segbase = s * SEGF;
    unsigned off[PER];
    #pragma unroll
    for (int j = 0; j < PER; j++) {
        int i = t + j * THREADS;
        int v = xrow[i * stride];      // low word either way (LE)
        off[j] = (unsigned)(v - segbase);
        if (off[j] < (unsigned)SEGF)
            atomicMax(&seg[off[j]], i);
    }
    __syncthreads();

    // --- Phase B: unique winner writes float bits + chunk flag.
    //     Weights > 0 => int bits > 2047 >= any position, distinguishable. ---
    #pragma unroll
    for (int j = 0; j < PER; j++) {
        int i = t + j * THREADS;
        if (off[j] < (unsigned)SEGF && seg[off[j]] == i) {
            seg[off[j]] = __float_as_int(e[j]);
            cflag[off[j] >> 7] = 1;    // benign race, same value
        }
    }
    __syncthreads();

    // --- fill: per warp-chunk, 1 broadcast LDS + 1 STG.128 per lane ---
    const int wid  = t >> 5;
    const int lane = t & 31;
    float* __restrict__ dst = out + (size_t)b * VDIM + segbase;
    const float4 z4 = make_float4(0.f, 0.f, 0.f, 0.f);
    #pragma unroll
    for (int k = 0; k < CPW; k++) {
        const int c = wid * CPW + k;
        float4* d = reinterpret_cast<float4*>(dst + c * CHUNKF) + lane;
        if (cflag[c] == 0) {
            *d = z4;                   // hot path: pure store
        } else {
            const int4* q = reinterpret_cast<const int4*>(seg + c * CHUNKF) + lane;
            int4 p = *q;
            float4 v;
            v.x = (p.x < 0) ? 0.0f : __int_as_float(p.x);
            v.y = (p.y < 0) ? 0.0f : __int_as_float(p.y);
            v.z = (p.z < 0) ? 0.0f : __int_as_float(p.z);
            v.w = (p.w < 0) ? 0.0f : __int_as_float(p.w);
            *d = v;
        }
    }

    // --- weights output (segment 0 only) ---
    if (s == 0) {
        long long wbase = (long long)BDIM * VDIM + (long long)b * SDIM;
        #pragma unroll
        for (int j = 0; j < PER; j++) {
            long long o = wbase + t + j * THREADS;
            if (o < out_elems) out[o] = e[j];
        }
    }
}

extern "C" void kernel_launch(void* const* d_in, const int* in_sizes, int n_in,
                              void* d_out, int out_size) {
    const float* w_es = (const float*)d_in[0];
    const int*   x32  = (const int*)d_in[1];
    float*       out  = (float*)d_out;
    (void)in_sizes; (void)n_in;
    dim3 grid(SEGS, BDIM);
    ohwa_cf_kernel<<<grid, THREADS>>>(w_es, x32, out, (long long)out_size);
}